// round 1
// baseline (speedup 1.0000x reference)
#include <cuda_runtime.h>

#define BATCH 4
#define TSEQ  2048
#define CEMB  1024
#define NHEAD 16
#define HDIM  64

// Scratch (allocation-free rule: __device__ globals)
__device__ float g_qkv[(size_t)BATCH * TSEQ * 3 * CEMB];   // [B,T,3C]
__device__ float g_att[(size_t)BATCH * TSEQ * CEMB];       // [B,T,C]

// ---------------------------------------------------------------------------
// SGEMM + bias: C[M,N] = A[M,K] @ B[K,N] + bias[N]
// 128x128 tile, BK=16, 256 threads, 8x8 micro-tile per thread. All dims are
// multiples of tile sizes for this problem, so no bounds checks.
// ---------------------------------------------------------------------------
#define BM 128
#define BN 128
#define BK 16

__global__ __launch_bounds__(256) void sgemm_bias_kernel(
    const float* __restrict__ A, const float* __restrict__ B,
    const float* __restrict__ bias, float* __restrict__ C,
    int M, int N, int K)
{
    __shared__ float As[BK][BM];   // A transposed in smem
    __shared__ float Bs[BK][BN];

    const int tid = threadIdx.x;
    const int tx = tid & 15;       // 0..15
    const int ty = tid >> 4;       // 0..15
    const int rowBase = blockIdx.y * BM;
    const int colBase = blockIdx.x * BN;

    float acc[8][8];
#pragma unroll
    for (int i = 0; i < 8; i++)
#pragma unroll
        for (int j = 0; j < 8; j++) acc[i][j] = 0.0f;

    // A tile load mapping: 128 rows x 16 cols, 2 threads per row, 8 floats each
    const int aRow = tid >> 1;           // 0..127
    const int aCol = (tid & 1) * 8;      // 0 or 8
    // B tile load mapping: 16 rows x 128 cols, 16 threads per row, 8 floats each
    const int bRow = tid >> 4;           // 0..15
    const int bCol = (tid & 15) * 8;     // 0..120

    const float* Arow = A + (size_t)(rowBase + aRow) * K;

    for (int k0 = 0; k0 < K; k0 += BK) {
        float4 a0 = *(const float4*)(Arow + k0 + aCol);
        float4 a1 = *(const float4*)(Arow + k0 + aCol + 4);
        As[aCol + 0][aRow] = a0.x;
        As[aCol + 1][aRow] = a0.y;
        As[aCol + 2][aRow] = a0.z;
        As[aCol + 3][aRow] = a0.w;
        As[aCol + 4][aRow] = a1.x;
        As[aCol + 5][aRow] = a1.y;
        As[aCol + 6][aRow] = a1.z;
        As[aCol + 7][aRow] = a1.w;

        const float* Brow = B + (size_t)(k0 + bRow) * N + colBase + bCol;
        *(float4*)&Bs[bRow][bCol]     = *(const float4*)(Brow);
        *(float4*)&Bs[bRow][bCol + 4] = *(const float4*)(Brow + 4);
        __syncthreads();

#pragma unroll
        for (int kk = 0; kk < BK; ++kk) {
            float ar[8], br[8];
            *(float4*)&ar[0] = *(const float4*)&As[kk][ty * 8];
            *(float4*)&ar[4] = *(const float4*)&As[kk][ty * 8 + 4];
            *(float4*)&br[0] = *(const float4*)&Bs[kk][tx * 8];
            *(float4*)&br[4] = *(const float4*)&Bs[kk][tx * 8 + 4];
#pragma unroll
            for (int i = 0; i < 8; i++)
#pragma unroll
                for (int j = 0; j < 8; j++)
                    acc[i][j] = fmaf(ar[i], br[j], acc[i][j]);
        }
        __syncthreads();
    }

    // Epilogue: += bias, vectorized stores
    float bv[8];
    *(float4*)&bv[0] = *(const float4*)&bias[colBase + tx * 8];
    *(float4*)&bv[4] = *(const float4*)&bias[colBase + tx * 8 + 4];
#pragma unroll
    for (int i = 0; i < 8; i++) {
        const size_t r = (size_t)(rowBase + ty * 8 + i);
        float4 v0, v1;
        v0.x = acc[i][0] + bv[0]; v0.y = acc[i][1] + bv[1];
        v0.z = acc[i][2] + bv[2]; v0.w = acc[i][3] + bv[3];
        v1.x = acc[i][4] + bv[4]; v1.y = acc[i][5] + bv[5];
        v1.z = acc[i][6] + bv[6]; v1.w = acc[i][7] + bv[7];
        *(float4*)&C[r * N + colBase + tx * 8]     = v0;
        *(float4*)&C[r * N + colBase + tx * 8 + 4] = v1;
    }
}

// ---------------------------------------------------------------------------
// fp32 flash attention, causal. Grid: (T/64, B*H). Block: 256 threads.
// 64 queries x 64 keys per tile, D=64. Online softmax. Q/K stored transposed
// [d][row] in smem; K buffer is reused for P after S is consumed.
// ---------------------------------------------------------------------------
__global__ __launch_bounds__(256) void flash_attn_kernel(
    const float* __restrict__ qkv, float* __restrict__ out)
{
    __shared__ float Qs[HDIM][64];    // [d][q]
    __shared__ float KPs[64][64];     // K: [d][k]  ->  P: [k][q]
    __shared__ float Vs[64][64];      // [k][d]

    const int tid = threadIdx.x;
    const int tx = tid & 15;          // col group
    const int ty = tid >> 4;          // row group
    const int qb = blockIdx.x;        // query block 0..31
    const int bh = blockIdx.y;        // 0..63
    const int b  = bh >> 4;
    const int h  = bh & 15;

    const size_t rowStride = 3 * CEMB;
    const float* base = qkv + (size_t)b * TSEQ * rowStride;
    const int qcol = h * HDIM;
    const int kcol = CEMB + h * HDIM;
    const int vcol = 2 * CEMB + h * HDIM;

    // Tile-load mapping: 64 rows, 4 threads/row, 16 floats each
    const int lr  = tid >> 2;         // 0..63
    const int ld0 = (tid & 3) * 16;   // 0,16,32,48

    // Load Q tile (transposed into smem)
    {
        const float* qp = base + (size_t)(qb * 64 + lr) * rowStride + qcol + ld0;
#pragma unroll
        for (int u = 0; u < 16; u += 4) {
            float4 v = *(const float4*)(qp + u);
            Qs[ld0 + u + 0][lr] = v.x;
            Qs[ld0 + u + 1][lr] = v.y;
            Qs[ld0 + u + 2][lr] = v.z;
            Qs[ld0 + u + 3][lr] = v.w;
        }
    }

    float o[4][4];
#pragma unroll
    for (int i = 0; i < 4; i++)
#pragma unroll
        for (int j = 0; j < 4; j++) o[i][j] = 0.0f;
    float m[4] = {-1e30f, -1e30f, -1e30f, -1e30f};
    float l[4] = {0.0f, 0.0f, 0.0f, 0.0f};

    const float SC = 0.125f;  // 1/sqrt(64)

    for (int kb = 0; kb <= qb; kb++) {
        __syncthreads();  // protect KPs/Vs (prior iter) and Qs (first iter)

        // Load K (transposed) and V (natural)
        {
            const float* kp = base + (size_t)(kb * 64 + lr) * rowStride + kcol + ld0;
            const float* vp = base + (size_t)(kb * 64 + lr) * rowStride + vcol + ld0;
#pragma unroll
            for (int u = 0; u < 16; u += 4) {
                float4 kv = *(const float4*)(kp + u);
                KPs[ld0 + u + 0][lr] = kv.x;
                KPs[ld0 + u + 1][lr] = kv.y;
                KPs[ld0 + u + 2][lr] = kv.z;
                KPs[ld0 + u + 3][lr] = kv.w;
                *(float4*)&Vs[lr][ld0 + u] = *(const float4*)(vp + u);
            }
        }
        __syncthreads();

        // S = Q @ K^T (4x4 per thread)
        float s[4][4];
#pragma unroll
        for (int i = 0; i < 4; i++)
#pragma unroll
            for (int j = 0; j < 4; j++) s[i][j] = 0.0f;
#pragma unroll
        for (int d = 0; d < HDIM; d++) {
            float4 qv = *(const float4*)&Qs[d][ty * 4];
            float4 kv = *(const float4*)&KPs[d][tx * 4];
            float qr[4] = {qv.x, qv.y, qv.z, qv.w};
            float kr[4] = {kv.x, kv.y, kv.z, kv.w};
#pragma unroll
            for (int i = 0; i < 4; i++)
#pragma unroll
                for (int j = 0; j < 4; j++)
                    s[i][j] = fmaf(qr[i], kr[j], s[i][j]);
        }

        // Scale + causal mask (only diagonal block needs masking)
        if (kb == qb) {
#pragma unroll
            for (int i = 0; i < 4; i++) {
                const int qg = ty * 4 + i;
#pragma unroll
                for (int j = 0; j < 4; j++) {
                    const int kg = tx * 4 + j;
                    s[i][j] = (kg <= qg) ? s[i][j] * SC : -1e30f;
                }
            }
        } else {
#pragma unroll
            for (int i = 0; i < 4; i++)
#pragma unroll
                for (int j = 0; j < 4; j++) s[i][j] *= SC;
        }

        // Online softmax update (row reductions across the 16 tx lanes)
#pragma unroll
        for (int i = 0; i < 4; i++) {
            float mt = fmaxf(fmaxf(s[i][0], s[i][1]), fmaxf(s[i][2], s[i][3]));
#pragma unroll
            for (int w = 1; w < 16; w <<= 1)
                mt = fmaxf(mt, __shfl_xor_sync(0xffffffffu, mt, w));
            const float mn = fmaxf(m[i], mt);
            const float alpha = __expf(m[i] - mn);
            m[i] = mn;
            float ls = 0.0f;
#pragma unroll
            for (int j = 0; j < 4; j++) {
                s[i][j] = __expf(s[i][j] - mn);
                ls += s[i][j];
            }
#pragma unroll
            for (int w = 1; w < 16; w <<= 1)
                ls += __shfl_xor_sync(0xffffffffu, ls, w);
            l[i] = l[i] * alpha + ls;
#pragma unroll
            for (int j = 0; j < 4; j++) o[i][j] *= alpha;
        }

        __syncthreads();  // everyone done reading KPs as K

        // Store P transposed: Ps[k][q]
#pragma unroll
        for (int i = 0; i < 4; i++)
#pragma unroll
            for (int j = 0; j < 4; j++)
                KPs[tx * 4 + j][ty * 4 + i] = s[i][j];
        __syncthreads();

        // O += P @ V
#pragma unroll
        for (int k = 0; k < 64; k++) {
            float4 pv = *(const float4*)&KPs[k][ty * 4];
            float4 vv = *(const float4*)&Vs[k][tx * 4];
            float pr[4] = {pv.x, pv.y, pv.z, pv.w};
            float vr[4] = {vv.x, vv.y, vv.z, vv.w};
#pragma unroll
            for (int i = 0; i < 4; i++)
#pragma unroll
                for (int j = 0; j < 4; j++)
                    o[i][j] = fmaf(pr[i], vr[j], o[i][j]);
        }
    }

    // Epilogue: normalize + store to [B,T,C] layout
#pragma unroll
    for (int i = 0; i < 4; i++) {
        const float inv = 1.0f / l[i];
        const int qg = qb * 64 + ty * 4 + i;
        float4 v;
        v.x = o[i][0] * inv; v.y = o[i][1] * inv;
        v.z = o[i][2] * inv; v.w = o[i][3] * inv;
        *(float4*)&out[((size_t)b * TSEQ + qg) * CEMB + h * HDIM + tx * 4] = v;
    }
}

// ---------------------------------------------------------------------------
extern "C" void kernel_launch(void* const* d_in, const int* in_sizes, int n_in,
                              void* d_out, int out_size)
{
    const float* x      = (const float*)d_in[0];
    const float* W_attn = (const float*)d_in[1];
    const float* b_attn = (const float*)d_in[2];
    const float* W_proj = (const float*)d_in[3];
    const float* b_proj = (const float*)d_in[4];
    float* out = (float*)d_out;

    float *qkv, *att;
    cudaGetSymbolAddress((void**)&qkv, g_qkv);
    cudaGetSymbolAddress((void**)&att, g_att);

    const int M = BATCH * TSEQ;  // 8192

    // 1) QKV projection: [8192,1024] @ [1024,3072] + b
    sgemm_bias_kernel<<<dim3((3 * CEMB) / BN, M / BM), 256>>>(
        x, W_attn, b_attn, qkv, M, 3 * CEMB, CEMB);

    // 2) Causal flash attention
    flash_attn_kernel<<<dim3(TSEQ / 64, BATCH * NHEAD), 256>>>(qkv, att);

    // 3) Output projection: [8192,1024] @ [1024,1024] + b
    sgemm_bias_kernel<<<dim3(CEMB / BN, M / BM), 256>>>(
        att, W_proj, b_proj, out, M, CEMB, CEMB);
}

// round 2
// speedup vs baseline: 1.0181x; 1.0181x over previous
#include <cuda_runtime.h>

#define BATCH 4
#define TSEQ  2048
#define CEMB  1024
#define NHEAD 16
#define HDIM  64

// Scratch (allocation-free rule: __device__ globals)
__device__ float g_qkv[(size_t)BATCH * TSEQ * 3 * CEMB];   // [B,T,3C]
__device__ float g_att[(size_t)BATCH * TSEQ * CEMB];       // [B,T,C]

// ---------------------------------------------------------------------------
// Packed fp32x2 helpers (SASS FFMA2 — ptxas never auto-fuses these)
// ---------------------------------------------------------------------------
typedef unsigned long long u64t;

__device__ __forceinline__ u64t ffma2(u64t a, u64t b, u64t c) {
    u64t d;
    asm("fma.rn.f32x2 %0, %1, %2, %3;" : "=l"(d) : "l"(a), "l"(b), "l"(c));
    return d;
}
__device__ __forceinline__ u64t mul2(u64t a, u64t b) {
    u64t d;
    asm("mul.rn.f32x2 %0, %1, %2;" : "=l"(d) : "l"(a), "l"(b));
    return d;
}
__device__ __forceinline__ u64t pk2(float x) {   // {x, x}
    u64t r;
    asm("mov.b64 %0, {%1, %1};" : "=l"(r) : "f"(x));
    return r;
}
__device__ __forceinline__ float2 upk(u64t v) {
    float2 f;
    asm("mov.b64 {%0, %1}, %2;" : "=f"(f.x), "=f"(f.y) : "l"(v));
    return f;
}

// ---------------------------------------------------------------------------
// SGEMM + bias: C[M,N] = A[M,K] @ B[K,N] + bias[N]
// 128x128 tile, BK=16, 256 threads, 8x8 micro-tile per thread, FFMA2 core.
// ---------------------------------------------------------------------------
#define BM 128
#define BN 128
#define BK 16

__global__ __launch_bounds__(256) void sgemm_bias_kernel(
    const float* __restrict__ A, const float* __restrict__ B,
    const float* __restrict__ bias, float* __restrict__ C,
    int M, int N, int K)
{
    __shared__ float As[BK][BM];   // A transposed in smem
    __shared__ float Bs[BK][BN];

    const int tid = threadIdx.x;
    const int tx = tid & 15;       // 0..15
    const int ty = tid >> 4;       // 0..15
    const int rowBase = blockIdx.y * BM;
    const int colBase = blockIdx.x * BN;

    u64t acc[8][4];                // 8 rows x 4 packed col-pairs
#pragma unroll
    for (int i = 0; i < 8; i++)
#pragma unroll
        for (int j = 0; j < 4; j++) acc[i][j] = 0ULL;

    const int aRow = tid >> 1;           // 0..127
    const int aCol = (tid & 1) * 8;      // 0 or 8
    const int bRow = tid >> 4;           // 0..15
    const int bCol = (tid & 15) * 8;     // 0..120

    const float* Arow = A + (size_t)(rowBase + aRow) * K;

    for (int k0 = 0; k0 < K; k0 += BK) {
        float4 a0 = *(const float4*)(Arow + k0 + aCol);
        float4 a1 = *(const float4*)(Arow + k0 + aCol + 4);
        As[aCol + 0][aRow] = a0.x;
        As[aCol + 1][aRow] = a0.y;
        As[aCol + 2][aRow] = a0.z;
        As[aCol + 3][aRow] = a0.w;
        As[aCol + 4][aRow] = a1.x;
        As[aCol + 5][aRow] = a1.y;
        As[aCol + 6][aRow] = a1.z;
        As[aCol + 7][aRow] = a1.w;

        const float* Brow = B + (size_t)(k0 + bRow) * N + colBase + bCol;
        *(float4*)&Bs[bRow][bCol]     = *(const float4*)(Brow);
        *(float4*)&Bs[bRow][bCol + 4] = *(const float4*)(Brow + 4);
        __syncthreads();

#pragma unroll
        for (int kk = 0; kk < BK; ++kk) {
            float ar[8];
            *(float4*)&ar[0] = *(const float4*)&As[kk][ty * 8];
            *(float4*)&ar[4] = *(const float4*)&As[kk][ty * 8 + 4];
            u64t br[4];
            br[0] = *(const u64t*)&Bs[kk][tx * 8 + 0];
            br[1] = *(const u64t*)&Bs[kk][tx * 8 + 2];
            br[2] = *(const u64t*)&Bs[kk][tx * 8 + 4];
            br[3] = *(const u64t*)&Bs[kk][tx * 8 + 6];
#pragma unroll
            for (int i = 0; i < 8; i++) {
                const u64t ap = pk2(ar[i]);
#pragma unroll
                for (int j = 0; j < 4; j++)
                    acc[i][j] = ffma2(ap, br[j], acc[i][j]);
            }
        }
        __syncthreads();
    }

    // Epilogue: unpack, += bias, vectorized stores
    float bv[8];
    *(float4*)&bv[0] = *(const float4*)&bias[colBase + tx * 8];
    *(float4*)&bv[4] = *(const float4*)&bias[colBase + tx * 8 + 4];
#pragma unroll
    for (int i = 0; i < 8; i++) {
        const size_t r = (size_t)(rowBase + ty * 8 + i);
        float2 c0 = upk(acc[i][0]);
        float2 c1 = upk(acc[i][1]);
        float2 c2 = upk(acc[i][2]);
        float2 c3 = upk(acc[i][3]);
        float4 v0, v1;
        v0.x = c0.x + bv[0]; v0.y = c0.y + bv[1];
        v0.z = c1.x + bv[2]; v0.w = c1.y + bv[3];
        v1.x = c2.x + bv[4]; v1.y = c2.y + bv[5];
        v1.z = c3.x + bv[6]; v1.w = c3.y + bv[7];
        *(float4*)&C[r * N + colBase + tx * 8]     = v0;
        *(float4*)&C[r * N + colBase + tx * 8 + 4] = v1;
    }
}

// ---------------------------------------------------------------------------
// fp32 flash attention, causal, FFMA2 inner products.
// Grid: (T/64, B*H). Block: 256 threads. 64q x 64k tiles, D=64.
// ---------------------------------------------------------------------------
__global__ __launch_bounds__(256) void flash_attn_kernel(
    const float* __restrict__ qkv, float* __restrict__ out)
{
    __shared__ float Qs[HDIM][64];    // [d][q]
    __shared__ float KPs[64][64];     // K: [d][k]  ->  P: [k][q]
    __shared__ float Vs[64][64];      // [k][d]

    const int tid = threadIdx.x;
    const int tx = tid & 15;          // col group
    const int ty = tid >> 4;          // row group
    const int qb = blockIdx.x;        // query block 0..31
    const int bh = blockIdx.y;        // 0..63
    const int b  = bh >> 4;
    const int h  = bh & 15;

    const size_t rowStride = 3 * CEMB;
    const float* base = qkv + (size_t)b * TSEQ * rowStride;
    const int qcol = h * HDIM;
    const int kcol = CEMB + h * HDIM;
    const int vcol = 2 * CEMB + h * HDIM;

    const int lr  = tid >> 2;         // 0..63
    const int ld0 = (tid & 3) * 16;   // 0,16,32,48

    // Load Q tile (transposed into smem)
    {
        const float* qp = base + (size_t)(qb * 64 + lr) * rowStride + qcol + ld0;
#pragma unroll
        for (int u = 0; u < 16; u += 4) {
            float4 v = *(const float4*)(qp + u);
            Qs[ld0 + u + 0][lr] = v.x;
            Qs[ld0 + u + 1][lr] = v.y;
            Qs[ld0 + u + 2][lr] = v.z;
            Qs[ld0 + u + 3][lr] = v.w;
        }
    }

    u64t o2[4][2];
#pragma unroll
    for (int i = 0; i < 4; i++) { o2[i][0] = 0ULL; o2[i][1] = 0ULL; }
    float m[4] = {-1e30f, -1e30f, -1e30f, -1e30f};
    float l[4] = {0.0f, 0.0f, 0.0f, 0.0f};

    const float SC = 0.125f;  // 1/sqrt(64)

    for (int kb = 0; kb <= qb; kb++) {
        __syncthreads();  // protect KPs/Vs (prior iter) and Qs (first iter)

        // Load K (transposed) and V (natural)
        {
            const float* kp = base + (size_t)(kb * 64 + lr) * rowStride + kcol + ld0;
            const float* vp = base + (size_t)(kb * 64 + lr) * rowStride + vcol + ld0;
#pragma unroll
            for (int u = 0; u < 16; u += 4) {
                float4 kv = *(const float4*)(kp + u);
                KPs[ld0 + u + 0][lr] = kv.x;
                KPs[ld0 + u + 1][lr] = kv.y;
                KPs[ld0 + u + 2][lr] = kv.z;
                KPs[ld0 + u + 3][lr] = kv.w;
                *(float4*)&Vs[lr][ld0 + u] = *(const float4*)(vp + u);
            }
        }
        __syncthreads();

        // S = Q @ K^T (4x4 per thread, packed pairs along k)
        u64t s2[4][2];
#pragma unroll
        for (int i = 0; i < 4; i++) { s2[i][0] = 0ULL; s2[i][1] = 0ULL; }
#pragma unroll
        for (int d = 0; d < HDIM; d++) {
            float4 qv = *(const float4*)&Qs[d][ty * 4];
            u64t k0 = *(const u64t*)&KPs[d][tx * 4 + 0];
            u64t k1 = *(const u64t*)&KPs[d][tx * 4 + 2];
            float qr[4] = {qv.x, qv.y, qv.z, qv.w};
#pragma unroll
            for (int i = 0; i < 4; i++) {
                const u64t qp2 = pk2(qr[i]);
                s2[i][0] = ffma2(qp2, k0, s2[i][0]);
                s2[i][1] = ffma2(qp2, k1, s2[i][1]);
            }
        }

        // Unpack, scale + causal mask
        float s[4][4];
#pragma unroll
        for (int i = 0; i < 4; i++) {
            float2 lo = upk(s2[i][0]);
            float2 hi = upk(s2[i][1]);
            s[i][0] = lo.x; s[i][1] = lo.y; s[i][2] = hi.x; s[i][3] = hi.y;
        }
        if (kb == qb) {
#pragma unroll
            for (int i = 0; i < 4; i++) {
                const int qg = ty * 4 + i;
#pragma unroll
                for (int j = 0; j < 4; j++) {
                    const int kg = tx * 4 + j;
                    s[i][j] = (kg <= qg) ? s[i][j] * SC : -1e30f;
                }
            }
        } else {
#pragma unroll
            for (int i = 0; i < 4; i++)
#pragma unroll
                for (int j = 0; j < 4; j++) s[i][j] *= SC;
        }

        // Online softmax update (row reductions across the 16 tx lanes)
#pragma unroll
        for (int i = 0; i < 4; i++) {
            float mt = fmaxf(fmaxf(s[i][0], s[i][1]), fmaxf(s[i][2], s[i][3]));
#pragma unroll
            for (int w = 1; w < 16; w <<= 1)
                mt = fmaxf(mt, __shfl_xor_sync(0xffffffffu, mt, w));
            const float mn = fmaxf(m[i], mt);
            const float alpha = __expf(m[i] - mn);
            m[i] = mn;
            float ls = 0.0f;
#pragma unroll
            for (int j = 0; j < 4; j++) {
                s[i][j] = __expf(s[i][j] - mn);
                ls += s[i][j];
            }
#pragma unroll
            for (int w = 1; w < 16; w <<= 1)
                ls += __shfl_xor_sync(0xffffffffu, ls, w);
            l[i] = l[i] * alpha + ls;
            const u64t ap = pk2(alpha);
            o2[i][0] = mul2(o2[i][0], ap);
            o2[i][1] = mul2(o2[i][1], ap);
        }

        __syncthreads();  // everyone done reading KPs as K

        // Store P transposed: Ps[k][q]
#pragma unroll
        for (int i = 0; i < 4; i++)
#pragma unroll
            for (int j = 0; j < 4; j++)
                KPs[tx * 4 + j][ty * 4 + i] = s[i][j];
        __syncthreads();

        // O += P @ V (packed pairs along d)
#pragma unroll
        for (int k = 0; k < 64; k++) {
            float4 pv = *(const float4*)&KPs[k][ty * 4];
            u64t v0 = *(const u64t*)&Vs[k][tx * 4 + 0];
            u64t v1 = *(const u64t*)&Vs[k][tx * 4 + 2];
            float pr[4] = {pv.x, pv.y, pv.z, pv.w};
#pragma unroll
            for (int i = 0; i < 4; i++) {
                const u64t pp = pk2(pr[i]);
                o2[i][0] = ffma2(pp, v0, o2[i][0]);
                o2[i][1] = ffma2(pp, v1, o2[i][1]);
            }
        }
    }

    // Epilogue: normalize + store to [B,T,C] layout
#pragma unroll
    for (int i = 0; i < 4; i++) {
        const float inv = 1.0f / l[i];
        const int qg = qb * 64 + ty * 4 + i;
        float2 a = upk(o2[i][0]);
        float2 c = upk(o2[i][1]);
        float4 v;
        v.x = a.x * inv; v.y = a.y * inv;
        v.z = c.x * inv; v.w = c.y * inv;
        *(float4*)&out[((size_t)b * TSEQ + qg) * CEMB + h * HDIM + tx * 4] = v;
    }
}

// ---------------------------------------------------------------------------
extern "C" void kernel_launch(void* const* d_in, const int* in_sizes, int n_in,
                              void* d_out, int out_size)
{
    const float* x      = (const float*)d_in[0];
    const float* W_attn = (const float*)d_in[1];
    const float* b_attn = (const float*)d_in[2];
    const float* W_proj = (const float*)d_in[3];
    const float* b_proj = (const float*)d_in[4];
    float* out = (float*)d_out;

    float *qkv, *att;
    cudaGetSymbolAddress((void**)&qkv, g_qkv);
    cudaGetSymbolAddress((void**)&att, g_att);

    const int M = BATCH * TSEQ;  // 8192

    // 1) QKV projection: [8192,1024] @ [1024,3072] + b
    sgemm_bias_kernel<<<dim3((3 * CEMB) / BN, M / BM), 256>>>(
        x, W_attn, b_attn, qkv, M, 3 * CEMB, CEMB);

    // 2) Causal flash attention
    flash_attn_kernel<<<dim3(TSEQ / 64, BATCH * NHEAD), 256>>>(qkv, att);

    // 3) Output projection: [8192,1024] @ [1024,1024] + b
    sgemm_bias_kernel<<<dim3(CEMB / BN, M / BM), 256>>>(
        att, W_proj, b_proj, out, M, CEMB, CEMB);
}

// round 3
// speedup vs baseline: 1.4826x; 1.4562x over previous
#include <cuda_runtime.h>
#include <cuda_bf16.h>

#define BATCH 4
#define TSEQ  2048
#define CEMB  1024
#define NHEAD 16
#define HDIM  64

// Scratch (allocation-free rule: __device__ globals)
__device__ float g_qkv[(size_t)BATCH * TSEQ * 3 * CEMB];   // [B,T,3C]
__device__ float g_att[(size_t)BATCH * TSEQ * CEMB];       // [B,T,C]

typedef unsigned u32t;
typedef unsigned long long u64t;

// ---------------------------------------------------------------------------
// Packed fp32x2 helpers (used by the attention kernel)
// ---------------------------------------------------------------------------
__device__ __forceinline__ u64t ffma2(u64t a, u64t b, u64t c) {
    u64t d;
    asm("fma.rn.f32x2 %0, %1, %2, %3;" : "=l"(d) : "l"(a), "l"(b), "l"(c));
    return d;
}
__device__ __forceinline__ u64t mul2(u64t a, u64t b) {
    u64t d;
    asm("mul.rn.f32x2 %0, %1, %2;" : "=l"(d) : "l"(a), "l"(b));
    return d;
}
__device__ __forceinline__ u64t pk2(float x) {
    u64t r;
    asm("mov.b64 %0, {%1, %1};" : "=l"(r) : "f"(x));
    return r;
}
__device__ __forceinline__ float2 upk(u64t v) {
    float2 f;
    asm("mov.b64 {%0, %1}, %2;" : "=f"(f.x), "=f"(f.y) : "l"(v));
    return f;
}

// ---------------------------------------------------------------------------
// Tensor-core helpers
// ---------------------------------------------------------------------------
__device__ __forceinline__ void ldsm4(u32t* r, u32t addr) {
    asm volatile("ldmatrix.sync.aligned.m8n8.x4.shared.b16 {%0,%1,%2,%3}, [%4];"
                 : "=r"(r[0]), "=r"(r[1]), "=r"(r[2]), "=r"(r[3]) : "r"(addr));
}
__device__ __forceinline__ void ldsm4t(u32t* r, u32t addr) {
    asm volatile("ldmatrix.sync.aligned.m8n8.x4.trans.shared.b16 {%0,%1,%2,%3}, [%4];"
                 : "=r"(r[0]), "=r"(r[1]), "=r"(r[2]), "=r"(r[3]) : "r"(addr));
}
__device__ __forceinline__ void mma16816(float* c, const u32t* a, const u32t* b) {
    asm volatile("mma.sync.aligned.m16n8k16.row.col.f32.bf16.bf16.f32 "
                 "{%0,%1,%2,%3}, {%4,%5,%6,%7}, {%8,%9}, {%0,%1,%2,%3};"
                 : "+f"(c[0]), "+f"(c[1]), "+f"(c[2]), "+f"(c[3])
                 : "r"(a[0]), "r"(a[1]), "r"(a[2]), "r"(a[3]),
                   "r"(b[0]), "r"(b[1]));
}
// pack two floats' bf16 hi parts into one u32 (low word = first element)
__device__ __forceinline__ u32t pbf2(float a, float b) {
    __nv_bfloat162 t;
    t.x = __float2bfloat16_rn(a);
    t.y = __float2bfloat16_rn(b);
    return *(u32t*)&t;
}
__device__ __forceinline__ float bres(float x) {  // residual after bf16 hi
    return x - __bfloat162float(__float2bfloat16_rn(x));
}

// ---------------------------------------------------------------------------
// Tensor-core GEMM + bias via bf16 split (Ah@Bh + Ah@Bl + Al@Bh).
// C[M,N] = A[M,K] @ B[K,N] + bias[N].  128x128 CTA tile, BK=32, 256 thr,
// 8 warps as 2(m) x 4(n), each warp 64x32 via 4x4 m16n8k16 tiles.
// ---------------------------------------------------------------------------
#define GBK 32
#define APAD 8
#define BPAD 8

__global__ __launch_bounds__(256) void hgemm_split_kernel(
    const float* __restrict__ A, const float* __restrict__ B,
    const float* __restrict__ bias, float* __restrict__ C,
    int M, int N, int K)
{
    __shared__ __nv_bfloat16 Ah[128][GBK + APAD];
    __shared__ __nv_bfloat16 Al[128][GBK + APAD];
    __shared__ __nv_bfloat16 Bh[GBK][128 + BPAD];
    __shared__ __nv_bfloat16 Bl[GBK][128 + BPAD];

    const int tid = threadIdx.x;
    const int lane = tid & 31;
    const int warp = tid >> 5;
    const int wm = warp >> 2;            // 0..1
    const int wn = warp & 3;             // 0..3
    const int mBase = wm * 64;
    const int nBase = wn * 32;
    const int rowBase = blockIdx.y * 128;
    const int colBase = blockIdx.x * 128;

    // global load mappings
    const int aRow = tid >> 1;           // 0..127
    const int aCol = (tid & 1) * 16;     // 0 or 16
    const int bRow = tid >> 3;           // 0..31
    const int bCol = (tid & 7) * 16;     // 0..112

    const float* Ap = A + (size_t)(rowBase + aRow) * K + aCol;
    const float* Bp = B + (size_t)bRow * N + colBase + bCol;

    float acc[4][4][4];
#pragma unroll
    for (int i = 0; i < 4; i++)
#pragma unroll
        for (int j = 0; j < 4; j++)
#pragma unroll
            for (int e = 0; e < 4; e++) acc[i][j][e] = 0.0f;

    for (int k0 = 0; k0 < K; k0 += GBK) {
        __syncthreads();
        // ---- stage A tile (convert fp32 -> bf16 hi/lo) ----
#pragma unroll
        for (int u = 0; u < 4; u++) {
            float4 v = *(const float4*)(Ap + k0 + u * 4);
            const int c = aCol + u * 4;
            *(u32t*)&Ah[aRow][c]     = pbf2(v.x, v.y);
            *(u32t*)&Ah[aRow][c + 2] = pbf2(v.z, v.w);
            *(u32t*)&Al[aRow][c]     = pbf2(bres(v.x), bres(v.y));
            *(u32t*)&Al[aRow][c + 2] = pbf2(bres(v.z), bres(v.w));
        }
        // ---- stage B tile ----
#pragma unroll
        for (int u = 0; u < 4; u++) {
            float4 v = *(const float4*)(Bp + (size_t)k0 * N + u * 4);
            const int c = bCol + u * 4;
            *(u32t*)&Bh[bRow][c]     = pbf2(v.x, v.y);
            *(u32t*)&Bh[bRow][c + 2] = pbf2(v.z, v.w);
            *(u32t*)&Bl[bRow][c]     = pbf2(bres(v.x), bres(v.y));
            *(u32t*)&Bl[bRow][c + 2] = pbf2(bres(v.z), bres(v.w));
        }
        __syncthreads();

        // ---- compute: two k16 steps ----
#pragma unroll
        for (int kk = 0; kk < GBK; kk += 16) {
            u32t ah[4][4], al[4][4], bh[4][2], bl[4][2];
            const int ar = (lane & 15);
            const int ac = kk + (lane >> 4) * 8;
#pragma unroll
            for (int mt = 0; mt < 4; mt++) {
                ldsm4(ah[mt], (u32t)__cvta_generic_to_shared(
                    &Ah[mBase + mt * 16 + ar][ac]));
                ldsm4(al[mt], (u32t)__cvta_generic_to_shared(
                    &Al[mBase + mt * 16 + ar][ac]));
            }
            const int br = kk + (lane & 15);
#pragma unroll
            for (int nt16 = 0; nt16 < 2; nt16++) {
                const int bc = nBase + nt16 * 16 + (lane >> 4) * 8;
                u32t t[4];
                ldsm4t(t, (u32t)__cvta_generic_to_shared(&Bh[br][bc]));
                bh[nt16 * 2][0] = t[0]; bh[nt16 * 2][1] = t[1];
                bh[nt16 * 2 + 1][0] = t[2]; bh[nt16 * 2 + 1][1] = t[3];
                ldsm4t(t, (u32t)__cvta_generic_to_shared(&Bl[br][bc]));
                bl[nt16 * 2][0] = t[0]; bl[nt16 * 2][1] = t[1];
                bl[nt16 * 2 + 1][0] = t[2]; bl[nt16 * 2 + 1][1] = t[3];
            }
#pragma unroll
            for (int mt = 0; mt < 4; mt++)
#pragma unroll
                for (int nt = 0; nt < 4; nt++) {
                    mma16816(acc[mt][nt], ah[mt], bh[nt]);
                    mma16816(acc[mt][nt], ah[mt], bl[nt]);
                    mma16816(acc[mt][nt], al[mt], bh[nt]);
                }
        }
    }

    // ---- epilogue: bias + store ----
#pragma unroll
    for (int nt = 0; nt < 4; nt++) {
        const int cg = colBase + nBase + nt * 8 + (lane & 3) * 2;
        const float2 bv = *(const float2*)&bias[cg];
#pragma unroll
        for (int mt = 0; mt < 4; mt++) {
            const int r0 = rowBase + mBase + mt * 16 + (lane >> 2);
            float2 v0, v1;
            v0.x = acc[mt][nt][0] + bv.x; v0.y = acc[mt][nt][1] + bv.y;
            v1.x = acc[mt][nt][2] + bv.x; v1.y = acc[mt][nt][3] + bv.y;
            *(float2*)&C[(size_t)r0 * N + cg]       = v0;
            *(float2*)&C[(size_t)(r0 + 8) * N + cg] = v1;
        }
    }
}

// ---------------------------------------------------------------------------
// fp32 flash attention, causal, FFMA2 inner products (unchanged from R2).
// ---------------------------------------------------------------------------
__global__ __launch_bounds__(256) void flash_attn_kernel(
    const float* __restrict__ qkv, float* __restrict__ out)
{
    __shared__ float Qs[HDIM][64];
    __shared__ float KPs[64][64];
    __shared__ float Vs[64][64];

    const int tid = threadIdx.x;
    const int tx = tid & 15;
    const int ty = tid >> 4;
    const int qb = blockIdx.x;
    const int bh = blockIdx.y;
    const int b  = bh >> 4;
    const int h  = bh & 15;

    const size_t rowStride = 3 * CEMB;
    const float* base = qkv + (size_t)b * TSEQ * rowStride;
    const int qcol = h * HDIM;
    const int kcol = CEMB + h * HDIM;
    const int vcol = 2 * CEMB + h * HDIM;

    const int lr  = tid >> 2;
    const int ld0 = (tid & 3) * 16;

    {
        const float* qp = base + (size_t)(qb * 64 + lr) * rowStride + qcol + ld0;
#pragma unroll
        for (int u = 0; u < 16; u += 4) {
            float4 v = *(const float4*)(qp + u);
            Qs[ld0 + u + 0][lr] = v.x;
            Qs[ld0 + u + 1][lr] = v.y;
            Qs[ld0 + u + 2][lr] = v.z;
            Qs[ld0 + u + 3][lr] = v.w;
        }
    }

    u64t o2[4][2];
#pragma unroll
    for (int i = 0; i < 4; i++) { o2[i][0] = 0ULL; o2[i][1] = 0ULL; }
    float m[4] = {-1e30f, -1e30f, -1e30f, -1e30f};
    float l[4] = {0.0f, 0.0f, 0.0f, 0.0f};

    const float SC = 0.125f;

    for (int kb = 0; kb <= qb; kb++) {
        __syncthreads();
        {
            const float* kp = base + (size_t)(kb * 64 + lr) * rowStride + kcol + ld0;
            const float* vp = base + (size_t)(kb * 64 + lr) * rowStride + vcol + ld0;
#pragma unroll
            for (int u = 0; u < 16; u += 4) {
                float4 kv = *(const float4*)(kp + u);
                KPs[ld0 + u + 0][lr] = kv.x;
                KPs[ld0 + u + 1][lr] = kv.y;
                KPs[ld0 + u + 2][lr] = kv.z;
                KPs[ld0 + u + 3][lr] = kv.w;
                *(float4*)&Vs[lr][ld0 + u] = *(const float4*)(vp + u);
            }
        }
        __syncthreads();

        u64t s2[4][2];
#pragma unroll
        for (int i = 0; i < 4; i++) { s2[i][0] = 0ULL; s2[i][1] = 0ULL; }
#pragma unroll
        for (int d = 0; d < HDIM; d++) {
            float4 qv = *(const float4*)&Qs[d][ty * 4];
            u64t k0 = *(const u64t*)&KPs[d][tx * 4 + 0];
            u64t k1 = *(const u64t*)&KPs[d][tx * 4 + 2];
            float qr[4] = {qv.x, qv.y, qv.z, qv.w};
#pragma unroll
            for (int i = 0; i < 4; i++) {
                const u64t qp2 = pk2(qr[i]);
                s2[i][0] = ffma2(qp2, k0, s2[i][0]);
                s2[i][1] = ffma2(qp2, k1, s2[i][1]);
            }
        }

        float s[4][4];
#pragma unroll
        for (int i = 0; i < 4; i++) {
            float2 lo = upk(s2[i][0]);
            float2 hi = upk(s2[i][1]);
            s[i][0] = lo.x; s[i][1] = lo.y; s[i][2] = hi.x; s[i][3] = hi.y;
        }
        if (kb == qb) {
#pragma unroll
            for (int i = 0; i < 4; i++) {
                const int qg = ty * 4 + i;
#pragma unroll
                for (int j = 0; j < 4; j++) {
                    const int kg = tx * 4 + j;
                    s[i][j] = (kg <= qg) ? s[i][j] * SC : -1e30f;
                }
            }
        } else {
#pragma unroll
            for (int i = 0; i < 4; i++)
#pragma unroll
                for (int j = 0; j < 4; j++) s[i][j] *= SC;
        }

#pragma unroll
        for (int i = 0; i < 4; i++) {
            float mt = fmaxf(fmaxf(s[i][0], s[i][1]), fmaxf(s[i][2], s[i][3]));
#pragma unroll
            for (int w = 1; w < 16; w <<= 1)
                mt = fmaxf(mt, __shfl_xor_sync(0xffffffffu, mt, w));
            const float mn = fmaxf(m[i], mt);
            const float alpha = __expf(m[i] - mn);
            m[i] = mn;
            float ls = 0.0f;
#pragma unroll
            for (int j = 0; j < 4; j++) {
                s[i][j] = __expf(s[i][j] - mn);
                ls += s[i][j];
            }
#pragma unroll
            for (int w = 1; w < 16; w <<= 1)
                ls += __shfl_xor_sync(0xffffffffu, ls, w);
            l[i] = l[i] * alpha + ls;
            const u64t ap = pk2(alpha);
            o2[i][0] = mul2(o2[i][0], ap);
            o2[i][1] = mul2(o2[i][1], ap);
        }

        __syncthreads();

#pragma unroll
        for (int i = 0; i < 4; i++)
#pragma unroll
            for (int j = 0; j < 4; j++)
                KPs[tx * 4 + j][ty * 4 + i] = s[i][j];
        __syncthreads();

#pragma unroll
        for (int k = 0; k < 64; k++) {
            float4 pv = *(const float4*)&KPs[k][ty * 4];
            u64t v0 = *(const u64t*)&Vs[k][tx * 4 + 0];
            u64t v1 = *(const u64t*)&Vs[k][tx * 4 + 2];
            float pr[4] = {pv.x, pv.y, pv.z, pv.w};
#pragma unroll
            for (int i = 0; i < 4; i++) {
                const u64t pp = pk2(pr[i]);
                o2[i][0] = ffma2(pp, v0, o2[i][0]);
                o2[i][1] = ffma2(pp, v1, o2[i][1]);
            }
        }
    }

#pragma unroll
    for (int i = 0; i < 4; i++) {
        const float inv = 1.0f / l[i];
        const int qg = qb * 64 + ty * 4 + i;
        float2 a = upk(o2[i][0]);
        float2 c = upk(o2[i][1]);
        float4 v;
        v.x = a.x * inv; v.y = a.y * inv;
        v.z = c.x * inv; v.w = c.y * inv;
        *(float4*)&out[((size_t)b * TSEQ + qg) * CEMB + h * HDIM + tx * 4] = v;
    }
}

// ---------------------------------------------------------------------------
extern "C" void kernel_launch(void* const* d_in, const int* in_sizes, int n_in,
                              void* d_out, int out_size)
{
    const float* x      = (const float*)d_in[0];
    const float* W_attn = (const float*)d_in[1];
    const float* b_attn = (const float*)d_in[2];
    const float* W_proj = (const float*)d_in[3];
    const float* b_proj = (const float*)d_in[4];
    float* out = (float*)d_out;

    float *qkv, *att;
    cudaGetSymbolAddress((void**)&qkv, g_qkv);
    cudaGetSymbolAddress((void**)&att, g_att);

    const int M = BATCH * TSEQ;  // 8192

    // 1) QKV projection: [8192,1024] @ [1024,3072] + b
    hgemm_split_kernel<<<dim3((3 * CEMB) / 128, M / 128), 256>>>(
        x, W_attn, b_attn, qkv, M, 3 * CEMB, CEMB);

    // 2) Causal flash attention
    flash_attn_kernel<<<dim3(TSEQ / 64, BATCH * NHEAD), 256>>>(qkv, att);

    // 3) Output projection: [8192,1024] @ [1024,1024] + b
    hgemm_split_kernel<<<dim3(CEMB / 128, M / 128), 256>>>(
        att, W_proj, b_proj, out, M, CEMB, CEMB);
}

// round 7
// speedup vs baseline: 2.5680x; 1.7321x over previous
#include <cuda_runtime.h>
#include <cuda_bf16.h>

#define BATCH 4
#define TSEQ  2048
#define CEMB  1024
#define NHEAD 16
#define HDIM  64

__device__ float g_qkv[(size_t)BATCH * TSEQ * 3 * CEMB];   // [B,T,3C]
__device__ float g_att[(size_t)BATCH * TSEQ * CEMB];       // [B,T,C]

typedef unsigned u32t;

// ---------------------------------------------------------------------------
// Tensor-core helpers (proven in R3)
// ---------------------------------------------------------------------------
__device__ __forceinline__ void ldsm4(u32t* r, u32t addr) {
    asm volatile("ldmatrix.sync.aligned.m8n8.x4.shared.b16 {%0,%1,%2,%3}, [%4];"
                 : "=r"(r[0]), "=r"(r[1]), "=r"(r[2]), "=r"(r[3]) : "r"(addr));
}
__device__ __forceinline__ void ldsm4t(u32t* r, u32t addr) {
    asm volatile("ldmatrix.sync.aligned.m8n8.x4.trans.shared.b16 {%0,%1,%2,%3}, [%4];"
                 : "=r"(r[0]), "=r"(r[1]), "=r"(r[2]), "=r"(r[3]) : "r"(addr));
}
__device__ __forceinline__ void mma16816(float* c, const u32t* a, const u32t* b) {
    asm volatile("mma.sync.aligned.m16n8k16.row.col.f32.bf16.bf16.f32 "
                 "{%0,%1,%2,%3}, {%4,%5,%6,%7}, {%8,%9}, {%0,%1,%2,%3};"
                 : "+f"(c[0]), "+f"(c[1]), "+f"(c[2]), "+f"(c[3])
                 : "r"(a[0]), "r"(a[1]), "r"(a[2]), "r"(a[3]),
                   "r"(b[0]), "r"(b[1]));
}
__device__ __forceinline__ u32t pbf2(float a, float b) {
    __nv_bfloat162 t;
    t.x = __float2bfloat16_rn(a);
    t.y = __float2bfloat16_rn(b);
    return *(u32t*)&t;
}
__device__ __forceinline__ float bres(float x) {
    return x - __bfloat162float(__float2bfloat16_rn(x));
}
__device__ __forceinline__ float ex2f(float x) {
    float y;
    asm("ex2.approx.f32 %0, %1;" : "=f"(y) : "f"(x));
    return y;
}

// ---------------------------------------------------------------------------
// Tensor-core GEMM + bias via bf16 split (unchanged from R3).
// ---------------------------------------------------------------------------
#define GBK 32
#define APAD 8
#define BPAD 8

__global__ __launch_bounds__(256) void hgemm_split_kernel(
    const float* __restrict__ A, const float* __restrict__ B,
    const float* __restrict__ bias, float* __restrict__ C,
    int M, int N, int K)
{
    __shared__ __nv_bfloat16 Ah[128][GBK + APAD];
    __shared__ __nv_bfloat16 Al[128][GBK + APAD];
    __shared__ __nv_bfloat16 Bh[GBK][128 + BPAD];
    __shared__ __nv_bfloat16 Bl[GBK][128 + BPAD];

    const int tid = threadIdx.x;
    const int lane = tid & 31;
    const int warp = tid >> 5;
    const int wm = warp >> 2;
    const int wn = warp & 3;
    const int mBase = wm * 64;
    const int nBase = wn * 32;
    const int rowBase = blockIdx.y * 128;
    const int colBase = blockIdx.x * 128;

    const int aRow = tid >> 1;
    const int aCol = (tid & 1) * 16;
    const int bRow = tid >> 3;
    const int bCol = (tid & 7) * 16;

    const float* Ap = A + (size_t)(rowBase + aRow) * K + aCol;
    const float* Bp = B + (size_t)bRow * N + colBase + bCol;

    float acc[4][4][4];
#pragma unroll
    for (int i = 0; i < 4; i++)
#pragma unroll
        for (int j = 0; j < 4; j++)
#pragma unroll
            for (int e = 0; e < 4; e++) acc[i][j][e] = 0.0f;

    for (int k0 = 0; k0 < K; k0 += GBK) {
        __syncthreads();
#pragma unroll
        for (int u = 0; u < 4; u++) {
            float4 v = *(const float4*)(Ap + k0 + u * 4);
            const int c = aCol + u * 4;
            *(u32t*)&Ah[aRow][c]     = pbf2(v.x, v.y);
            *(u32t*)&Ah[aRow][c + 2] = pbf2(v.z, v.w);
            *(u32t*)&Al[aRow][c]     = pbf2(bres(v.x), bres(v.y));
            *(u32t*)&Al[aRow][c + 2] = pbf2(bres(v.z), bres(v.w));
        }
#pragma unroll
        for (int u = 0; u < 4; u++) {
            float4 v = *(const float4*)(Bp + (size_t)k0 * N + u * 4);
            const int c = bCol + u * 4;
            *(u32t*)&Bh[bRow][c]     = pbf2(v.x, v.y);
            *(u32t*)&Bh[bRow][c + 2] = pbf2(v.z, v.w);
            *(u32t*)&Bl[bRow][c]     = pbf2(bres(v.x), bres(v.y));
            *(u32t*)&Bl[bRow][c + 2] = pbf2(bres(v.z), bres(v.w));
        }
        __syncthreads();

#pragma unroll
        for (int kk = 0; kk < GBK; kk += 16) {
            u32t ah[4][4], al[4][4], bh[4][2], bl[4][2];
            const int ar = (lane & 15);
            const int ac = kk + (lane >> 4) * 8;
#pragma unroll
            for (int mt = 0; mt < 4; mt++) {
                ldsm4(ah[mt], (u32t)__cvta_generic_to_shared(
                    &Ah[mBase + mt * 16 + ar][ac]));
                ldsm4(al[mt], (u32t)__cvta_generic_to_shared(
                    &Al[mBase + mt * 16 + ar][ac]));
            }
            const int br = kk + (lane & 15);
#pragma unroll
            for (int nt16 = 0; nt16 < 2; nt16++) {
                const int bc = nBase + nt16 * 16 + (lane >> 4) * 8;
                u32t t[4];
                ldsm4t(t, (u32t)__cvta_generic_to_shared(&Bh[br][bc]));
                bh[nt16 * 2][0] = t[0]; bh[nt16 * 2][1] = t[1];
                bh[nt16 * 2 + 1][0] = t[2]; bh[nt16 * 2 + 1][1] = t[3];
                ldsm4t(t, (u32t)__cvta_generic_to_shared(&Bl[br][bc]));
                bl[nt16 * 2][0] = t[0]; bl[nt16 * 2][1] = t[1];
                bl[nt16 * 2 + 1][0] = t[2]; bl[nt16 * 2 + 1][1] = t[3];
            }
#pragma unroll
            for (int mt = 0; mt < 4; mt++)
#pragma unroll
                for (int nt = 0; nt < 4; nt++) {
                    mma16816(acc[mt][nt], ah[mt], bh[nt]);
                    mma16816(acc[mt][nt], ah[mt], bl[nt]);
                    mma16816(acc[mt][nt], al[mt], bh[nt]);
                }
        }
    }

#pragma unroll
    for (int nt = 0; nt < 4; nt++) {
        const int cg = colBase + nBase + nt * 8 + (lane & 3) * 2;
        const float2 bv = *(const float2*)&bias[cg];
#pragma unroll
        for (int mt = 0; mt < 4; mt++) {
            const int r0 = rowBase + mBase + mt * 16 + (lane >> 2);
            float2 v0, v1;
            v0.x = acc[mt][nt][0] + bv.x; v0.y = acc[mt][nt][1] + bv.y;
            v1.x = acc[mt][nt][2] + bv.x; v1.y = acc[mt][nt][3] + bv.y;
            *(float2*)&C[(size_t)r0 * N + cg]       = v0;
            *(float2*)&C[(size_t)(r0 + 8) * N + cg] = v1;
        }
    }
}

// ---------------------------------------------------------------------------
// Tensor-core flash attention, causal, bf16 split.
// Grid: (T/128, B*H). 256 threads = 8 warps; warp w owns q-rows [16w,16w+16)
// of the 128-row Q block and the full 64-key tile. P stays in registers
// (C-fragment -> A-fragment identity).
// ---------------------------------------------------------------------------
#define SSTR 72   // smem row stride (elements)

__global__ __launch_bounds__(256) void flash_attn_tc_kernel(
    const float* __restrict__ qkv, float* __restrict__ out)
{
    __shared__ __align__(16) char smraw[2 * 128 * SSTR * 2];  // 36864 B
    __nv_bfloat16* const Qh  = (__nv_bfloat16*)smraw;          // [128][SSTR]
    __nv_bfloat16* const Ql  = Qh + 128 * SSTR;
    __nv_bfloat16* const KTh = (__nv_bfloat16*)smraw;          // [64][SSTR] d-major
    __nv_bfloat16* const KTl = KTh + 64 * SSTR;
    __nv_bfloat16* const Vsh = KTl + 64 * SSTR;                // [64][SSTR] key-major
    __nv_bfloat16* const Vsl = Vsh + 64 * SSTR;

    const int tid  = threadIdx.x;
    const int lane = tid & 31;
    const int wid  = tid >> 5;
    const int bx   = blockIdx.x;            // q block of 128
    const int bh   = blockIdx.y;
    const int b    = bh >> 4;
    const int h    = bh & 15;

    const size_t rowStride = 3 * CEMB;
    const float* base = qkv + (size_t)b * TSEQ * rowStride;
    const int qcol = h * HDIM;
    const int kcol = CEMB + h * HDIM;
    const int vcol = 2 * CEMB + h * HDIM;

    // ---- stage Q (128x64) hi/lo ----
    {
        const int r  = tid >> 1;
        const int c0 = (tid & 1) * 32;
        const float* qp = base + (size_t)(bx * 128 + r) * rowStride + qcol + c0;
#pragma unroll
        for (int u = 0; u < 32; u += 4) {
            float4 v = *(const float4*)(qp + u);
            *(u32t*)&Qh[r * SSTR + c0 + u]     = pbf2(v.x, v.y);
            *(u32t*)&Qh[r * SSTR + c0 + u + 2] = pbf2(v.z, v.w);
            *(u32t*)&Ql[r * SSTR + c0 + u]     = pbf2(bres(v.x), bres(v.y));
            *(u32t*)&Ql[r * SSTR + c0 + u + 2] = pbf2(bres(v.z), bres(v.w));
        }
    }
    __syncthreads();

    // ---- Q fragments into registers (held for whole kernel) ----
    u32t qfh[4][4], qfl[4][4];
    {
        const int ar = wid * 16 + (lane & 15);
        const int ac = (lane >> 4) * 8;
#pragma unroll
        for (int kk = 0; kk < 4; kk++) {
            ldsm4(qfh[kk], (u32t)__cvta_generic_to_shared(&Qh[ar * SSTR + kk * 16 + ac]));
            ldsm4(qfl[kk], (u32t)__cvta_generic_to_shared(&Ql[ar * SSTR + kk * 16 + ac]));
        }
    }

    float oacc[8][4];
#pragma unroll
    for (int nt = 0; nt < 8; nt++)
#pragma unroll
        for (int e = 0; e < 4; e++) oacc[nt][e] = 0.0f;
    float mrow0 = -1e30f, mrow1 = -1e30f;
    float lrow0 = 0.0f, lrow1 = 0.0f;

    const float SC2 = 0.18033688011112042f;  // (1/8) * log2(e)
    const int r0g = bx * 128 + wid * 16 + (lane >> 2);   // global q row (c0/c1)

    const int nTiles = 2 * bx + 2;
    for (int kb = 0; kb < nTiles; kb++) {
        __syncthreads();   // prior-iter smem reads done (also covers Q frags first time)

        // ---- load K (transposed, hi/lo) and V (natural, hi/lo) ----
        {
            const int lr  = tid >> 2;             // key 0..63
            const int ld0 = (tid & 3) * 16;       // d offset
            const float* kp = base + (size_t)(kb * 64 + lr) * rowStride + kcol + ld0;
            const float* vp = base + (size_t)(kb * 64 + lr) * rowStride + vcol + ld0;
#pragma unroll
            for (int u = 0; u < 16; u += 4) {
                float4 kv = *(const float4*)(kp + u);
                KTh[(ld0 + u + 0) * SSTR + lr] = __float2bfloat16_rn(kv.x);
                KTh[(ld0 + u + 1) * SSTR + lr] = __float2bfloat16_rn(kv.y);
                KTh[(ld0 + u + 2) * SSTR + lr] = __float2bfloat16_rn(kv.z);
                KTh[(ld0 + u + 3) * SSTR + lr] = __float2bfloat16_rn(kv.w);
                KTl[(ld0 + u + 0) * SSTR + lr] = __float2bfloat16_rn(bres(kv.x));
                KTl[(ld0 + u + 1) * SSTR + lr] = __float2bfloat16_rn(bres(kv.y));
                KTl[(ld0 + u + 2) * SSTR + lr] = __float2bfloat16_rn(bres(kv.z));
                KTl[(ld0 + u + 3) * SSTR + lr] = __float2bfloat16_rn(bres(kv.w));
                float4 vv = *(const float4*)(vp + u);
                *(u32t*)&Vsh[lr * SSTR + ld0 + u]     = pbf2(vv.x, vv.y);
                *(u32t*)&Vsh[lr * SSTR + ld0 + u + 2] = pbf2(vv.z, vv.w);
                *(u32t*)&Vsl[lr * SSTR + ld0 + u]     = pbf2(bres(vv.x), bres(vv.y));
                *(u32t*)&Vsl[lr * SSTR + ld0 + u + 2] = pbf2(bres(vv.z), bres(vv.w));
            }
        }
        __syncthreads();

        // ---- S = Q @ K^T : warp computes 16x64 ----
        float sacc[8][4];
#pragma unroll
        for (int nt = 0; nt < 8; nt++)
#pragma unroll
            for (int e = 0; e < 4; e++) sacc[nt][e] = 0.0f;

#pragma unroll
        for (int kk = 0; kk < 4; kk++) {
            const int br = kk * 16 + (lane & 15);
            const int bc = (lane >> 4) * 8;
#pragma unroll
            for (int nt16 = 0; nt16 < 4; nt16++) {
                u32t th[4], tl[4];
                ldsm4t(th, (u32t)__cvta_generic_to_shared(&KTh[br * SSTR + nt16 * 16 + bc]));
                ldsm4t(tl, (u32t)__cvta_generic_to_shared(&KTl[br * SSTR + nt16 * 16 + bc]));
                mma16816(sacc[2 * nt16],     qfh[kk], th);
                mma16816(sacc[2 * nt16],     qfh[kk], tl);
                mma16816(sacc[2 * nt16],     qfl[kk], th);
                mma16816(sacc[2 * nt16 + 1], qfh[kk], th + 2);
                mma16816(sacc[2 * nt16 + 1], qfh[kk], tl + 2);
                mma16816(sacc[2 * nt16 + 1], qfl[kk], th + 2);
            }
        }

        // ---- scale to log2 domain + causal mask ----
        const bool diag = (kb >= 2 * bx);
#pragma unroll
        for (int nt = 0; nt < 8; nt++) {
            const int colg = kb * 64 + nt * 8 + (lane & 3) * 2;
#pragma unroll
            for (int e = 0; e < 4; e++) {
                float v = sacc[nt][e] * SC2;
                if (diag) {
                    const int row = r0g + ((e >= 2) ? 8 : 0);
                    const int col = colg + (e & 1);
                    if (col > row) v = -1e30f;
                }
                sacc[nt][e] = v;
            }
        }

        // ---- online softmax (log2 domain) ----
        float mx0 = -1e30f, mx1 = -1e30f;
#pragma unroll
        for (int nt = 0; nt < 8; nt++) {
            mx0 = fmaxf(mx0, fmaxf(sacc[nt][0], sacc[nt][1]));
            mx1 = fmaxf(mx1, fmaxf(sacc[nt][2], sacc[nt][3]));
        }
        mx0 = fmaxf(mx0, __shfl_xor_sync(0xffffffffu, mx0, 1));
        mx0 = fmaxf(mx0, __shfl_xor_sync(0xffffffffu, mx0, 2));
        mx1 = fmaxf(mx1, __shfl_xor_sync(0xffffffffu, mx1, 1));
        mx1 = fmaxf(mx1, __shfl_xor_sync(0xffffffffu, mx1, 2));

        const float mn0 = fmaxf(mrow0, mx0);
        const float mn1 = fmaxf(mrow1, mx1);
        const float a0 = ex2f(mrow0 - mn0);
        const float a1 = ex2f(mrow1 - mn1);
        mrow0 = mn0; mrow1 = mn1;

        float sum0 = 0.0f, sum1 = 0.0f;
#pragma unroll
        for (int nt = 0; nt < 8; nt++) {
            sacc[nt][0] = ex2f(sacc[nt][0] - mn0);
            sacc[nt][1] = ex2f(sacc[nt][1] - mn0);
            sacc[nt][2] = ex2f(sacc[nt][2] - mn1);
            sacc[nt][3] = ex2f(sacc[nt][3] - mn1);
            sum0 += sacc[nt][0] + sacc[nt][1];
            sum1 += sacc[nt][2] + sacc[nt][3];
        }
        sum0 += __shfl_xor_sync(0xffffffffu, sum0, 1);
        sum0 += __shfl_xor_sync(0xffffffffu, sum0, 2);
        sum1 += __shfl_xor_sync(0xffffffffu, sum1, 1);
        sum1 += __shfl_xor_sync(0xffffffffu, sum1, 2);
        lrow0 = lrow0 * a0 + sum0;
        lrow1 = lrow1 * a1 + sum1;

#pragma unroll
        for (int nt = 0; nt < 8; nt++) {
            oacc[nt][0] *= a0; oacc[nt][1] *= a0;
            oacc[nt][2] *= a1; oacc[nt][3] *= a1;
        }

        // ---- P fragments in-register (C-frag -> A-frag identity) ----
        u32t pfh[4][4], pfl[4][4];
#pragma unroll
        for (int kt = 0; kt < 4; kt++) {
            const float* c0 = sacc[2 * kt];
            const float* c1 = sacc[2 * kt + 1];
            pfh[kt][0] = pbf2(c0[0], c0[1]);
            pfh[kt][1] = pbf2(c0[2], c0[3]);
            pfh[kt][2] = pbf2(c1[0], c1[1]);
            pfh[kt][3] = pbf2(c1[2], c1[3]);
            pfl[kt][0] = pbf2(bres(c0[0]), bres(c0[1]));
            pfl[kt][1] = pbf2(bres(c0[2]), bres(c0[3]));
            pfl[kt][2] = pbf2(bres(c1[0]), bres(c1[1]));
            pfl[kt][3] = pbf2(bres(c1[2]), bres(c1[3]));
        }

        // ---- O += P @ V ----
#pragma unroll
        for (int kt = 0; kt < 4; kt++) {
            const int br = kt * 16 + (lane & 15);
            const int bc = (lane >> 4) * 8;
#pragma unroll
            for (int nt16 = 0; nt16 < 4; nt16++) {
                u32t th[4], tl[4];
                ldsm4t(th, (u32t)__cvta_generic_to_shared(&Vsh[br * SSTR + nt16 * 16 + bc]));
                ldsm4t(tl, (u32t)__cvta_generic_to_shared(&Vsl[br * SSTR + nt16 * 16 + bc]));
                mma16816(oacc[2 * nt16],     pfh[kt], th);
                mma16816(oacc[2 * nt16],     pfh[kt], tl);
                mma16816(oacc[2 * nt16],     pfl[kt], th);
                mma16816(oacc[2 * nt16 + 1], pfh[kt], th + 2);
                mma16816(oacc[2 * nt16 + 1], pfh[kt], tl + 2);
                mma16816(oacc[2 * nt16 + 1], pfl[kt], th + 2);
            }
        }
    }

    // ---- epilogue: normalize + store [B,T,C] ----
    const float inv0 = 1.0f / lrow0;
    const float inv1 = 1.0f / lrow1;
    const int row0 = bx * 128 + wid * 16 + (lane >> 2);
#pragma unroll
    for (int nt = 0; nt < 8; nt++) {
        const int col = h * HDIM + nt * 8 + (lane & 3) * 2;
        float2 v0, v1;
        v0.x = oacc[nt][0] * inv0; v0.y = oacc[nt][1] * inv0;
        v1.x = oacc[nt][2] * inv1; v1.y = oacc[nt][3] * inv1;
        *(float2*)&out[((size_t)b * TSEQ + row0) * CEMB + col]     = v0;
        *(float2*)&out[((size_t)b * TSEQ + row0 + 8) * CEMB + col] = v1;
    }
}

// ---------------------------------------------------------------------------
extern "C" void kernel_launch(void* const* d_in, const int* in_sizes, int n_in,
                              void* d_out, int out_size)
{
    const float* x      = (const float*)d_in[0];
    const float* W_attn = (const float*)d_in[1];
    const float* b_attn = (const float*)d_in[2];
    const float* W_proj = (const float*)d_in[3];
    const float* b_proj = (const float*)d_in[4];
    float* out = (float*)d_out;

    float *qkv, *att;
    cudaGetSymbolAddress((void**)&qkv, g_qkv);
    cudaGetSymbolAddress((void**)&att, g_att);

    const int M = BATCH * TSEQ;  // 8192

    // 1) QKV projection
    hgemm_split_kernel<<<dim3((3 * CEMB) / 128, M / 128), 256>>>(
        x, W_attn, b_attn, qkv, M, 3 * CEMB, CEMB);

    // 2) Causal flash attention (tensor cores)
    flash_attn_tc_kernel<<<dim3(TSEQ / 128, BATCH * NHEAD), 256>>>(qkv, att);

    // 3) Output projection
    hgemm_split_kernel<<<dim3(CEMB / 128, M / 128), 256>>>(
        att, W_proj, b_proj, out, M, CEMB, CEMB);
}